// round 8
// baseline (speedup 1.0000x reference)
#include <cuda_runtime.h>
#include <cuda_bf16.h>
#include <cstdint>

#define MAXN 50000
#define MAXE 800000
#define NB 148            // persistent preproc blocks (1 per SM, co-resident)
#define BT 256

// ---------------- scratch (device globals: no allocation allowed) ----------
__device__ __align__(16) int   g_deg[MAXN];
__device__ __align__(16) int   g_cursor[MAXN];
__device__ __align__(16) int   g_rowptr[MAXN + 2];
__device__ __align__(16) float g_dis[MAXN];
__device__ __align__(16) int   g_bsum[NB + 2];
__device__ __align__(16) int   g_col[MAXE];
__device__ __align__(16) float g_w[MAXE];
__device__ __align__(16) float g_h1[(size_t)MAXN * 128];
__device__ __align__(16) float g_h2[(size_t)MAXN * 128];
// tf32 hi/lo W fragments: L1 hi@0 lo@8192 | L2 hi@16384 lo@32768 | L3 hi@49152 lo@57344
__device__ __align__(16) float g_wfrag[65536];
__device__ unsigned g_arrive = 0;   // monotonic grid-barrier ticket counter

__device__ __forceinline__ const float* buf_in(int sel)  { return sel == 0 ? g_h1 : g_h2; }
__device__ __forceinline__ float*       buf_out(int sel) { return sel == 0 ? g_h1 : g_h2; }

__device__ __forceinline__ float tf32_rna(float x) {
    unsigned r;
    asm("cvt.rna.tf32.f32 %0, %1;" : "=r"(r) : "f"(x));
    return __uint_as_float(r);
}

__device__ __forceinline__ void mma_tf32(float c[4], float2 A0, float2 A1, float2 B) {
    asm volatile(
        "mma.sync.aligned.m16n8k8.row.col.f32.tf32.tf32.f32 "
        "{%0,%1,%2,%3}, {%4,%5,%6,%7}, {%8,%9}, {%0,%1,%2,%3};"
        : "+f"(c[0]), "+f"(c[1]), "+f"(c[2]), "+f"(c[3])
        : "r"(__float_as_uint(A0.x)), "r"(__float_as_uint(A1.x)),
          "r"(__float_as_uint(A0.y)), "r"(__float_as_uint(A1.y)),
          "r"(__float_as_uint(B.x)),  "r"(__float_as_uint(B.y)));
}

// Software grid barrier. Monotonic tickets: barrier k completes when the
// counter reaches k*NB; after a full launch (5 barriers) the counter ends
// at a multiple of NB, so replays keep working. All NB blocks are resident
// (1 per SM) so no deadlock.
__device__ __forceinline__ void gbar() {
    __syncthreads();
    if (threadIdx.x == 0) {
        __threadfence();
        unsigned ticket = atomicAdd(&g_arrive, 1u) + 1u;
        unsigned target = ((ticket + NB - 1u) / NB) * NB;
        while (atomicAdd(&g_arrive, 0u) < target) __nanosleep(64);
    }
    __syncthreads();
    __threadfence();
}

// ---------------- fused preprocessing (one persistent kernel) --------------
__global__ void __launch_bounds__(BT) k_preproc(
        const int* __restrict__ src, const int* __restrict__ dst,
        const float* __restrict__ W1, const float* __restrict__ W2,
        const float* __restrict__ W3, int E, int n) {
    __shared__ int sh[BT];
    const int tid = threadIdx.x;
    const int bid = blockIdx.x;
    const int gthreads = NB * BT;
    const int gtid = bid * BT + tid;
    const int CH = (n + NB - 1) / NB;                // nodes per block
    const int cbeg = bid * CH;
    const int cend = min(cbeg + CH, n);

    // ---- P0: zero deg/cursor + build W fragments ----
    for (int i = gtid; i < n; i += gthreads) { g_deg[i] = 0; g_cursor[i] = 0; }
    {
        int i = gtid;                                 // 37888 threads >= 32768
        if (i < 32768) {
            const float* W; int OUT, base, rel, inout;
            if (i < 8192)       { W = W1; OUT = 128; base = 0;     rel = i;         inout = 8192; }
            else if (i < 24576) { W = W2; OUT = 128; base = 16384; rel = i - 8192;  inout = 16384; }
            else                { W = W3; OUT = 64;  base = 49152; rel = i - 24576; inout = 8192; }
            int k = rel / OUT, c = rel % OUT;
            float w = W[rel];
            float hi = tf32_rna(w);
            float lo = tf32_rna(w - hi);
            int t = k & 3, slot = (k >> 2) & 1;
            int kc = k >> 4, kk = (k >> 3) & 1;
            int off = (((kc * 2 + kk) * OUT + c) << 3) + (t << 1) + slot;
            g_wfrag[base + off] = hi;
            g_wfrag[base + inout + off] = lo;
        }
    }
    gbar();

    // ---- P1: degree count ----
    for (int i = gtid; i < E; i += gthreads) {
        unsigned d = (unsigned)dst[i];
        if (d < (unsigned)n) atomicAdd(&g_deg[d], 1);
    }
    gbar();

    // ---- P2: dis + per-block chunk sums ----
    {
        int s = 0;
        for (int i = cbeg + tid; i < cend; i += BT) {
            int dg = g_deg[i];
            g_dis[i] = rsqrtf((float)(dg + 1));
            s += dg;
        }
        sh[tid] = s;
        __syncthreads();
        for (int off = BT / 2; off > 0; off >>= 1) {
            if (tid < off) sh[tid] += sh[tid + off];
            __syncthreads();
        }
        if (tid == 0) g_bsum[bid] = sh[0];
    }
    gbar();

    // ---- P3: block 0 scans the NB block sums (exclusive) ----
    if (bid == 0) {
        int v = (tid < NB) ? g_bsum[tid] : 0;
        sh[tid] = v;
        __syncthreads();
        for (int off = 1; off < BT; off <<= 1) {
            int u = (tid >= off) ? sh[tid - off] : 0;
            __syncthreads();
            sh[tid] += u;
            __syncthreads();
        }
        if (tid < NB) g_bsum[tid] = sh[tid] - v;     // exclusive
        if (tid == NB - 1) g_rowptr[n] = sh[tid];    // total
    }
    gbar();

    // ---- P4: per-block exclusive rescan -> rowptr ----
    {
        constexpr int PER = 2;                        // ceil(338/256)
        int tbeg = cbeg + tid * PER;
        int s = 0;
        int loc[PER];
#pragma unroll
        for (int q = 0; q < PER; q++) {
            int i = tbeg + q;
            int dg = (i < cend) ? g_deg[i] : 0;
            loc[q] = s;
            s += dg;
        }
        sh[tid] = s;
        __syncthreads();
        for (int off = 1; off < BT; off <<= 1) {
            int u = (tid >= off) ? sh[tid - off] : 0;
            __syncthreads();
            sh[tid] += u;
            __syncthreads();
        }
        int base = g_bsum[bid] + sh[tid] - s;         // exclusive thread base
#pragma unroll
        for (int q = 0; q < PER; q++) {
            int i = tbeg + q;
            if (i < cend) g_rowptr[i] = base + loc[q];
        }
    }
    gbar();

    // ---- P5: CSR fill ----
    for (int i = gtid; i < E; i += gthreads) {
        unsigned s = (unsigned)src[i];
        unsigned d = (unsigned)dst[i];
        if (s < (unsigned)n && d < (unsigned)n) {
            int pos = g_rowptr[d] + atomicAdd(&g_cursor[d], 1);
            g_col[pos] = (int)s;
            g_w[pos] = g_dis[s] * g_dis[d];
        }
    }
}

// ---------------- aggregation: one warp per node ----------------------------
__global__ void k_agg128(int n) {
    int warp = (blockIdx.x * blockDim.x + threadIdx.x) >> 5;
    int lane = threadIdx.x & 31;
    if (warp >= n) return;
    const float* in = g_h2;
    float ds = g_dis[warp];
    float self = ds * ds;
    float4 v = ((const float4*)(in + (size_t)warp * 128))[lane];
    float4 acc = make_float4(self * v.x, self * v.y, self * v.z, self * v.w);
    int beg = g_rowptr[warp], end = g_rowptr[warp + 1];
    for (int base = beg; base < end; base += 32) {
        int idx = base + lane;
        int c = 0; float wv = 0.f;
        if (idx < end) { c = g_col[idx]; wv = g_w[idx]; }
        int m = min(32, end - base);
        for (int t = 0; t < m; t++) {
            int s   = __shfl_sync(0xffffffffu, c, t);
            float w = __shfl_sync(0xffffffffu, wv, t);
            float4 u = ((const float4*)(in + (size_t)s * 128))[lane];
            acc.x += w * u.x; acc.y += w * u.y; acc.z += w * u.z; acc.w += w * u.w;
        }
    }
    ((float4*)(g_h1 + (size_t)warp * 128))[lane] = acc;
}

__global__ void k_agg64_first(const float* __restrict__ in, int n) {
    int warp = (blockIdx.x * blockDim.x + threadIdx.x) >> 5;
    int lane = threadIdx.x & 31;
    if (warp >= n) return;
    float ds = g_dis[warp];
    float self = ds * ds;
    float2 v = ((const float2*)(in + (size_t)warp * 64))[lane];
    float2 acc = make_float2(self * v.x, self * v.y);
    int beg = g_rowptr[warp], end = g_rowptr[warp + 1];
    for (int base = beg; base < end; base += 32) {
        int idx = base + lane;
        int c = 0; float wv = 0.f;
        if (idx < end) { c = g_col[idx]; wv = g_w[idx]; }
        int m = min(32, end - base);
        for (int t = 0; t < m; t++) {
            int s   = __shfl_sync(0xffffffffu, c, t);
            float w = __shfl_sync(0xffffffffu, wv, t);
            float2 u = ((const float2*)(in + (size_t)s * 64))[lane];
            acc.x += w * u.x; acc.y += w * u.y;
        }
    }
    ((float2*)(g_h1 + (size_t)warp * 64))[lane] = acc;
}

__global__ void k_agg64_last(float* __restrict__ out,
                             const float* __restrict__ bias, int n) {
    int warp = (blockIdx.x * blockDim.x + threadIdx.x) >> 5;
    int lane = threadIdx.x & 31;
    if (warp >= n) return;
    const float* in = g_h1;
    float ds = g_dis[warp];
    float self = ds * ds;
    float2 v = ((const float2*)(in + (size_t)warp * 64))[lane];
    float2 acc = make_float2(self * v.x, self * v.y);
    int beg = g_rowptr[warp], end = g_rowptr[warp + 1];
    for (int base = beg; base < end; base += 32) {
        int idx = base + lane;
        int c = 0; float wv = 0.f;
        if (idx < end) { c = g_col[idx]; wv = g_w[idx]; }
        int m = min(32, end - base);
        for (int t = 0; t < m; t++) {
            int s   = __shfl_sync(0xffffffffu, c, t);
            float w = __shfl_sync(0xffffffffu, wv, t);
            float2 u = ((const float2*)(in + (size_t)s * 64))[lane];
            acc.x += w * u.x; acc.y += w * u.y;
        }
    }
    acc.x += bias[lane * 2];
    acc.y += bias[lane * 2 + 1];
    ((float2*)(out + (size_t)warp * 64))[lane] = acc;
}

// ---------------- tensor-core GEMM (3xTF32) ---------------------------------
template <int IN, int OUT, bool BIAS, bool RELU>
__global__ void __launch_bounds__(128) k_gemm_tc(int insel, int outsel,
        const float* __restrict__ bias, int wfb, int n) {
    constexpr int NT = OUT / 8;
    __shared__ float XFh[2 * 128 * 8];
    __shared__ float XFl[2 * 128 * 8];
    __shared__ float WFh[2 * OUT * 8];
    __shared__ float WFl[2 * OUT * 8];

    const float* X = buf_in(insel);
    float* Y = buf_out(outsel);
    const float* WH = g_wfrag + wfb;
    const float* WL = WH + IN * OUT;

    int tid = threadIdx.x;
    int w = tid >> 5, lane = tid & 31, g = lane >> 2, t = lane & 3;
    int row0 = blockIdx.x * 128;

    float acc[2][NT][4];
#pragma unroll
    for (int m = 0; m < 2; m++)
#pragma unroll
        for (int nt = 0; nt < NT; nt++)
#pragma unroll
            for (int q = 0; q < 4; q++) acc[m][nt][q] = 0.f;

    for (int kc = 0; kc < IN / 16; kc++) {
#pragma unroll
        for (int f = 0; f < 4; f++) {
            int fid = tid + f * 128;
            int r = fid >> 2;
            int j = fid & 3;
            float4 v = make_float4(0.f, 0.f, 0.f, 0.f);
            int gr = row0 + r;
            if (gr < n) v = *(const float4*)(X + (size_t)gr * IN + kc * 16 + j * 4);
            int kk = j >> 1, slot = j & 1;
            int b = kk * 1024 + r * 8 + slot;
            float h0 = tf32_rna(v.x), h1 = tf32_rna(v.y);
            float h2 = tf32_rna(v.z), h3 = tf32_rna(v.w);
            XFh[b + 0] = h0; XFh[b + 2] = h1; XFh[b + 4] = h2; XFh[b + 6] = h3;
            XFl[b + 0] = tf32_rna(v.x - h0); XFl[b + 2] = tf32_rna(v.y - h1);
            XFl[b + 4] = tf32_rna(v.z - h2); XFl[b + 6] = tf32_rna(v.w - h3);
        }
        {
            const float4* sh_ = (const float4*)(WH + kc * OUT * 16);
            const float4* sl_ = (const float4*)(WL + kc * OUT * 16);
            float4* dh = (float4*)WFh;
            float4* dl = (float4*)WFl;
            for (int f = tid; f < OUT * 4; f += 128) { dh[f] = sh_[f]; dl[f] = sl_[f]; }
        }
        __syncthreads();

#pragma unroll
        for (int kk = 0; kk < 2; kk++) {
            float2 ah[2][2], al[2][2];
#pragma unroll
            for (int m = 0; m < 2; m++) {
                int r = w * 32 + m * 16 + g;
                ah[m][0] = *(const float2*)(XFh + kk * 1024 + r * 8 + t * 2);
                ah[m][1] = *(const float2*)(XFh + kk * 1024 + (r + 8) * 8 + t * 2);
                al[m][0] = *(const float2*)(XFl + kk * 1024 + r * 8 + t * 2);
                al[m][1] = *(const float2*)(XFl + kk * 1024 + (r + 8) * 8 + t * 2);
            }
#pragma unroll
            for (int nt = 0; nt < NT; nt++) {
                int nb = kk * OUT * 8 + (nt * 8 + g) * 8 + t * 2;
                float2 bh = *(const float2*)(WFh + nb);
                float2 bl = *(const float2*)(WFl + nb);
#pragma unroll
                for (int m = 0; m < 2; m++) {
                    mma_tf32(acc[m][nt], ah[m][0], ah[m][1], bh);
                    mma_tf32(acc[m][nt], ah[m][0], ah[m][1], bl);
                    mma_tf32(acc[m][nt], al[m][0], al[m][1], bh);
                }
            }
        }
        __syncthreads();
    }

#pragma unroll
    for (int m = 0; m < 2; m++) {
        int r = row0 + w * 32 + m * 16 + g;
#pragma unroll
        for (int nt = 0; nt < NT; nt++) {
            int c = nt * 8 + t * 2;
            float2 p0 = make_float2(acc[m][nt][0], acc[m][nt][1]);
            float2 p1 = make_float2(acc[m][nt][2], acc[m][nt][3]);
            if (BIAS) {
                float2 bb = *(const float2*)(bias + c);
                p0.x += bb.x; p0.y += bb.y; p1.x += bb.x; p1.y += bb.y;
            }
            if (RELU) {
                p0.x = fmaxf(p0.x, 0.f); p0.y = fmaxf(p0.y, 0.f);
                p1.x = fmaxf(p1.x, 0.f); p1.y = fmaxf(p1.y, 0.f);
            }
            if (r < n)     *(float2*)(Y + (size_t)r * OUT + c) = p0;
            if (r + 8 < n) *(float2*)(Y + (size_t)(r + 8) * OUT + c) = p1;
        }
    }
}

// ---------------- launch ----------------------------------------------------
extern "C" void kernel_launch(void* const* d_in, const int* in_sizes, int n_in,
                              void* d_out, int out_size) {
    const float* x  = (const float*)d_in[0];
    const int*   ei = (const int*)d_in[1];   // int32 (JAX x64 disabled)
    const float* W1 = (const float*)d_in[2];
    const float* b1 = (const float*)d_in[3];
    const float* W2 = (const float*)d_in[4];
    const float* b2 = (const float*)d_in[5];
    const float* W3 = (const float*)d_in[6];
    const float* b3 = (const float*)d_in[7];
    float* out = (float*)d_out;

    const int n = in_sizes[0] / 64;   // 50000
    const int E = in_sizes[1] / 2;    // 800000
    const int* src = ei;
    const int* dst = ei + E;

    // --- fused CSR build + normalization + W fragments (one kernel) ---
    k_preproc<<<NB, BT>>>(src, dst, W1, W2, W3, E, n);

    const int aggGrid = (n + 7) / 8;      // 8 warps/block
    const int gemmGrid = (n + 127) / 128; // 391

    // Layer 1: (A x)[64] @ W1 -> relu -> g_h2[128]
    k_agg64_first<<<aggGrid, 256>>>(x, n);
    k_gemm_tc<64, 128, true, true><<<gemmGrid, 128>>>(0, 1, b1, 0, n);

    // Layer 2: (A g_h2)[128] @ W2 -> relu -> g_h2[128]
    k_agg128<<<aggGrid, 256>>>(n);
    k_gemm_tc<128, 128, true, true><<<gemmGrid, 128>>>(0, 1, b2, 16384, n);

    // Layer 3: (g_h2 @ W3)[64] -> aggregate -> + b3 -> out
    k_gemm_tc<128, 64, false, false><<<gemmGrid, 128>>>(1, 0, nullptr, 49152, n);
    k_agg64_last<<<aggGrid, 256>>>(out, b3, n);
}

// round 9
// speedup vs baseline: 1.0740x; 1.0740x over previous
#include <cuda_runtime.h>
#include <cuda_fp16.h>
#include <cstdint>

#define MAXN 50000
#define MAXE 800000
#define SCAN_B 256
#define MAX_SCAN_BLOCKS ((MAXN + SCAN_B - 1) / SCAN_B)   // 196

// ---------------- scratch (device globals: no allocation allowed) ----------
__device__ __align__(16) int   g_deg[MAXN];
__device__ __align__(16) int   g_cursor[MAXN];
__device__ __align__(16) int   g_rowptr[MAXN + 2];
__device__ __align__(16) float g_dis[MAXN];
__device__ __align__(16) int   g_bsum[MAX_SCAN_BLOCKS + 1];
__device__ __align__(16) int   g_col[MAXE];
__device__ __align__(16) float g_w[MAXE];
__device__ __align__(16) float g_h1[(size_t)MAXN * 128];
__device__ __align__(16) float g_h2[(size_t)MAXN * 128];
__device__ __align__(16) __half g_f16[(size_t)MAXN * 128];  // fp16 agg operand
// tf32 hi/lo W fragments: L1 hi@0 lo@8192 | L2 hi@16384 lo@32768 | L3 hi@49152 lo@57344
__device__ __align__(16) float g_wfrag[65536];

__device__ __forceinline__ const float* buf_in(int sel)  { return sel == 0 ? g_h1 : g_h2; }
__device__ __forceinline__ float*       buf_out(int sel) { return sel == 0 ? g_h1 : g_h2; }

__device__ __forceinline__ float tf32_rna(float x) {
    unsigned r;
    asm("cvt.rna.tf32.f32 %0, %1;" : "=r"(r) : "f"(x));
    return __uint_as_float(r);
}

__device__ __forceinline__ void mma_tf32(float c[4], float2 A0, float2 A1, float2 B) {
    asm volatile(
        "mma.sync.aligned.m16n8k8.row.col.f32.tf32.tf32.f32 "
        "{%0,%1,%2,%3}, {%4,%5,%6,%7}, {%8,%9}, {%0,%1,%2,%3};"
        : "+f"(c[0]), "+f"(c[1]), "+f"(c[2]), "+f"(c[3])
        : "r"(__float_as_uint(A0.x)), "r"(__float_as_uint(A1.x)),
          "r"(__float_as_uint(A0.y)), "r"(__float_as_uint(A1.y)),
          "r"(__float_as_uint(B.x)),  "r"(__float_as_uint(B.y)));
}

// ---------------- preprocessing (round-7 layout: separate small kernels) ----
__global__ void k_zero(int n) {
    int i = blockIdx.x * blockDim.x + threadIdx.x;
    if (i < n) { g_deg[i] = 0; g_cursor[i] = 0; }
}

__global__ void k_count(const int* __restrict__ dst, int E, int n) {
    int i = blockIdx.x * blockDim.x + threadIdx.x;
    if (i < E) {
        unsigned d = (unsigned)dst[i];
        if (d < (unsigned)n) atomicAdd(&g_deg[d], 1);
    }
}

__global__ void k_dis(int n) {
    int i = blockIdx.x * blockDim.x + threadIdx.x;
    if (i < n) g_dis[i] = rsqrtf((float)(g_deg[i] + 1));  // +1 self loop
}

__global__ void k_wprep(const float* __restrict__ W1,
                        const float* __restrict__ W2,
                        const float* __restrict__ W3) {
    int i = blockIdx.x * blockDim.x + threadIdx.x;   // 0..32767
    if (i >= 32768) return;
    const float* W; int OUT, base, rel, inout;
    if (i < 8192)       { W = W1; OUT = 128; base = 0;     rel = i;         inout = 8192; }
    else if (i < 24576) { W = W2; OUT = 128; base = 16384; rel = i - 8192;  inout = 16384; }
    else                { W = W3; OUT = 64;  base = 49152; rel = i - 24576; inout = 8192; }
    int k = rel / OUT, n = rel % OUT;
    float w = W[rel];
    float hi = tf32_rna(w);
    float lo = tf32_rna(w - hi);
    int t = k & 3, slot = (k >> 2) & 1;
    int kc = k >> 4, kk = (k >> 3) & 1;
    int off = (((kc * 2 + kk) * OUT + n) << 3) + (t << 1) + slot;
    g_wfrag[base + off] = hi;
    g_wfrag[base + inout + off] = lo;
}

// x (fp32, 64-wide) -> g_f16
__global__ void k_cvt64(const float* __restrict__ x, int n) {
    int i = blockIdx.x * blockDim.x + threadIdx.x;   // one float4 each
    if (i < n * 16) {
        float4 v = ((const float4*)x)[i];
        __half2* o = (__half2*)g_f16 + i * 2;
        o[0] = __floats2half2_rn(v.x, v.y);
        o[1] = __floats2half2_rn(v.z, v.w);
    }
}

__global__ void k_scanA(int n) {
    __shared__ int sh[SCAN_B];
    int i = blockIdx.x * SCAN_B + threadIdx.x;
    int v = (i < n) ? g_deg[i] : 0;
    sh[threadIdx.x] = v;
    __syncthreads();
    for (int off = SCAN_B / 2; off > 0; off >>= 1) {
        if (threadIdx.x < off) sh[threadIdx.x] += sh[threadIdx.x + off];
        __syncthreads();
    }
    if (threadIdx.x == 0) g_bsum[blockIdx.x] = sh[0];
}

__global__ void k_scanB(int nblocks, int n) {
    __shared__ int sh[SCAN_B];
    int t = threadIdx.x;
    int v = (t < nblocks) ? g_bsum[t] : 0;
    sh[t] = v;
    __syncthreads();
    for (int off = 1; off < SCAN_B; off <<= 1) {
        int u = (t >= off) ? sh[t - off] : 0;
        __syncthreads();
        sh[t] += u;
        __syncthreads();
    }
    if (t < nblocks) g_bsum[t] = sh[t] - v;
    if (t == nblocks - 1) g_rowptr[n] = sh[t];
}

__global__ void k_scanC(int n) {
    __shared__ int sh[SCAN_B];
    int i = blockIdx.x * SCAN_B + threadIdx.x;
    int t = threadIdx.x;
    int v = (i < n) ? g_deg[i] : 0;
    sh[t] = v;
    __syncthreads();
    for (int off = 1; off < SCAN_B; off <<= 1) {
        int u = (t >= off) ? sh[t - off] : 0;
        __syncthreads();
        sh[t] += u;
        __syncthreads();
    }
    if (i < n) g_rowptr[i] = sh[t] - v + g_bsum[blockIdx.x];
}

__global__ void k_fill(const int* __restrict__ src,
                       const int* __restrict__ dst, int E, int n) {
    int i = blockIdx.x * blockDim.x + threadIdx.x;
    if (i < E) {
        unsigned s = (unsigned)src[i];
        unsigned d = (unsigned)dst[i];
        if (s < (unsigned)n && d < (unsigned)n) {
            int pos = g_rowptr[d] + atomicAdd(&g_cursor[d], 1);
            g_col[pos] = (int)s;
            g_w[pos] = g_dis[s] * g_dis[d];
        }
    }
}

// ---------------- aggregation (fp16 gathers, fp32 accumulation) -------------
struct __align__(8) h4 { __half2 a, b; };

// 128-wide: reads g_f16, writes g_h1 (fp32)
__global__ void k_agg128(int n) {
    int warp = (blockIdx.x * blockDim.x + threadIdx.x) >> 5;
    int lane = threadIdx.x & 31;
    if (warp >= n) return;
    const __half* in = g_f16;
    float ds = g_dis[warp];
    float self = ds * ds;
    h4 sv = ((const h4*)(in + (size_t)warp * 128))[lane];
    float2 s0 = __half22float2(sv.a), s1 = __half22float2(sv.b);
    float4 acc = make_float4(self * s0.x, self * s0.y, self * s1.x, self * s1.y);
    int beg = g_rowptr[warp], end = g_rowptr[warp + 1];
    for (int base = beg; base < end; base += 32) {
        int idx = base + lane;
        int c = 0; float wv = 0.f;
        if (idx < end) { c = g_col[idx]; wv = g_w[idx]; }
        int m = min(32, end - base);
        for (int t = 0; t < m; t++) {
            int s   = __shfl_sync(0xffffffffu, c, t);
            float w = __shfl_sync(0xffffffffu, wv, t);
            h4 u = ((const h4*)(in + (size_t)s * 128))[lane];
            float2 f0 = __half22float2(u.a), f1 = __half22float2(u.b);
            acc.x += w * f0.x; acc.y += w * f0.y;
            acc.z += w * f1.x; acc.w += w * f1.y;
        }
    }
    ((float4*)(g_h1 + (size_t)warp * 128))[lane] = acc;
}

// 64-wide: reads g_f16, writes g_h1 (fp32)
__global__ void k_agg64_first(int n) {
    int warp = (blockIdx.x * blockDim.x + threadIdx.x) >> 5;
    int lane = threadIdx.x & 31;
    if (warp >= n) return;
    const __half* in = g_f16;
    float ds = g_dis[warp];
    float self = ds * ds;
    float2 v = __half22float2(((const __half2*)(in + (size_t)warp * 64))[lane]);
    float2 acc = make_float2(self * v.x, self * v.y);
    int beg = g_rowptr[warp], end = g_rowptr[warp + 1];
    for (int base = beg; base < end; base += 32) {
        int idx = base + lane;
        int c = 0; float wv = 0.f;
        if (idx < end) { c = g_col[idx]; wv = g_w[idx]; }
        int m = min(32, end - base);
        for (int t = 0; t < m; t++) {
            int s   = __shfl_sync(0xffffffffu, c, t);
            float w = __shfl_sync(0xffffffffu, wv, t);
            float2 u = __half22float2(((const __half2*)(in + (size_t)s * 64))[lane]);
            acc.x += w * u.x; acc.y += w * u.y;
        }
    }
    ((float2*)(g_h1 + (size_t)warp * 64))[lane] = acc;
}

// 64-wide last: reads g_f16, + b3, writes external out (fp32)
__global__ void k_agg64_last(float* __restrict__ out,
                             const float* __restrict__ bias, int n) {
    int warp = (blockIdx.x * blockDim.x + threadIdx.x) >> 5;
    int lane = threadIdx.x & 31;
    if (warp >= n) return;
    const __half* in = g_f16;
    float ds = g_dis[warp];
    float self = ds * ds;
    float2 v = __half22float2(((const __half2*)(in + (size_t)warp * 64))[lane]);
    float2 acc = make_float2(self * v.x, self * v.y);
    int beg = g_rowptr[warp], end = g_rowptr[warp + 1];
    for (int base = beg; base < end; base += 32) {
        int idx = base + lane;
        int c = 0; float wv = 0.f;
        if (idx < end) { c = g_col[idx]; wv = g_w[idx]; }
        int m = min(32, end - base);
        for (int t = 0; t < m; t++) {
            int s   = __shfl_sync(0xffffffffu, c, t);
            float w = __shfl_sync(0xffffffffu, wv, t);
            float2 u = __half22float2(((const __half2*)(in + (size_t)s * 64))[lane]);
            acc.x += w * u.x; acc.y += w * u.y;
        }
    }
    acc.x += bias[lane * 2];
    acc.y += bias[lane * 2 + 1];
    ((float2*)(out + (size_t)warp * 64))[lane] = acc;
}

// ---------------- tensor-core GEMM (3xTF32) ---------------------------------
// HALF_OUT: write half2 into g_f16 instead of fp32 buffer.
template <int IN, int OUT, bool BIAS, bool RELU, bool HALF_OUT>
__global__ void __launch_bounds__(128) k_gemm_tc(int insel, int outsel,
        const float* __restrict__ bias, int wfb, int n) {
    constexpr int NT = OUT / 8;
    __shared__ float XFh[2 * 128 * 8];
    __shared__ float XFl[2 * 128 * 8];
    __shared__ float WFh[2 * OUT * 8];
    __shared__ float WFl[2 * OUT * 8];

    const float* X = buf_in(insel);
    float* Y = buf_out(outsel);
    __half* Y16 = g_f16;
    const float* WH = g_wfrag + wfb;
    const float* WL = WH + IN * OUT;

    int tid = threadIdx.x;
    int w = tid >> 5, lane = tid & 31, g = lane >> 2, t = lane & 3;
    int row0 = blockIdx.x * 128;

    float acc[2][NT][4];
#pragma unroll
    for (int m = 0; m < 2; m++)
#pragma unroll
        for (int nt = 0; nt < NT; nt++)
#pragma unroll
            for (int q = 0; q < 4; q++) acc[m][nt][q] = 0.f;

    for (int kc = 0; kc < IN / 16; kc++) {
#pragma unroll
        for (int f = 0; f < 4; f++) {
            int fid = tid + f * 128;
            int r = fid >> 2;
            int j = fid & 3;
            float4 v = make_float4(0.f, 0.f, 0.f, 0.f);
            int gr = row0 + r;
            if (gr < n) v = *(const float4*)(X + (size_t)gr * IN + kc * 16 + j * 4);
            int kk = j >> 1, slot = j & 1;
            int b = kk * 1024 + r * 8 + slot;
            float h0 = tf32_rna(v.x), h1 = tf32_rna(v.y);
            float h2 = tf32_rna(v.z), h3 = tf32_rna(v.w);
            XFh[b + 0] = h0; XFh[b + 2] = h1; XFh[b + 4] = h2; XFh[b + 6] = h3;
            XFl[b + 0] = tf32_rna(v.x - h0); XFl[b + 2] = tf32_rna(v.y - h1);
            XFl[b + 4] = tf32_rna(v.z - h2); XFl[b + 6] = tf32_rna(v.w - h3);
        }
        {
            const float4* sh_ = (const float4*)(WH + kc * OUT * 16);
            const float4* sl_ = (const float4*)(WL + kc * OUT * 16);
            float4* dh = (float4*)WFh;
            float4* dl = (float4*)WFl;
            for (int f = tid; f < OUT * 4; f += 128) { dh[f] = sh_[f]; dl[f] = sl_[f]; }
        }
        __syncthreads();

#pragma unroll
        for (int kk = 0; kk < 2; kk++) {
            float2 ah[2][2], al[2][2];
#pragma unroll
            for (int m = 0; m < 2; m++) {
                int r = w * 32 + m * 16 + g;
                ah[m][0] = *(const float2*)(XFh + kk * 1024 + r * 8 + t * 2);
                ah[m][1] = *(const float2*)(XFh + kk * 1024 + (r + 8) * 8 + t * 2);
                al[m][0] = *(const float2*)(XFl + kk * 1024 + r * 8 + t * 2);
                al[m][1] = *(const float2*)(XFl + kk * 1024 + (r + 8) * 8 + t * 2);
            }
#pragma unroll
            for (int nt = 0; nt < NT; nt++) {
                int nb = kk * OUT * 8 + (nt * 8 + g) * 8 + t * 2;
                float2 bh = *(const float2*)(WFh + nb);
                float2 bl = *(const float2*)(WFl + nb);
#pragma unroll
                for (int m = 0; m < 2; m++) {
                    mma_tf32(acc[m][nt], ah[m][0], ah[m][1], bh);
                    mma_tf32(acc[m][nt], ah[m][0], ah[m][1], bl);
                    mma_tf32(acc[m][nt], al[m][0], al[m][1], bh);
                }
            }
        }
        __syncthreads();
    }

#pragma unroll
    for (int m = 0; m < 2; m++) {
        int r = row0 + w * 32 + m * 16 + g;
#pragma unroll
        for (int nt = 0; nt < NT; nt++) {
            int c = nt * 8 + t * 2;
            float2 p0 = make_float2(acc[m][nt][0], acc[m][nt][1]);
            float2 p1 = make_float2(acc[m][nt][2], acc[m][nt][3]);
            if (BIAS) {
                float2 bb = *(const float2*)(bias + c);
                p0.x += bb.x; p0.y += bb.y; p1.x += bb.x; p1.y += bb.y;
            }
            if (RELU) {
                p0.x = fmaxf(p0.x, 0.f); p0.y = fmaxf(p0.y, 0.f);
                p1.x = fmaxf(p1.x, 0.f); p1.y = fmaxf(p1.y, 0.f);
            }
            if (HALF_OUT) {
                if (r < n)
                    *(__half2*)(Y16 + (size_t)r * OUT + c) = __floats2half2_rn(p0.x, p0.y);
                if (r + 8 < n)
                    *(__half2*)(Y16 + (size_t)(r + 8) * OUT + c) = __floats2half2_rn(p1.x, p1.y);
            } else {
                if (r < n)     *(float2*)(Y + (size_t)r * OUT + c) = p0;
                if (r + 8 < n) *(float2*)(Y + (size_t)(r + 8) * OUT + c) = p1;
            }
        }
    }
}

// ---------------- launch ----------------------------------------------------
extern "C" void kernel_launch(void* const* d_in, const int* in_sizes, int n_in,
                              void* d_out, int out_size) {
    const float* x  = (const float*)d_in[0];
    const int*   ei = (const int*)d_in[1];   // int32 (JAX x64 disabled)
    const float* W1 = (const float*)d_in[2];
    const float* b1 = (const float*)d_in[3];
    const float* W2 = (const float*)d_in[4];
    const float* b2 = (const float*)d_in[5];
    const float* W3 = (const float*)d_in[6];
    const float* b3 = (const float*)d_in[7];
    float* out = (float*)d_out;

    const int n = in_sizes[0] / 64;   // 50000
    const int E = in_sizes[1] / 2;    // 800000
    const int* src = ei;
    const int* dst = ei + E;

    const int T = 256;
    const int scanBlocks = (n + SCAN_B - 1) / SCAN_B;   // 196

    // --- build CSR + normalization + W fragments + x->fp16 ---
    k_zero<<<(n + T - 1) / T, T>>>(n);
    k_count<<<(E + T - 1) / T, T>>>(dst, E, n);
    k_wprep<<<128, 256>>>(W1, W2, W3);
    k_cvt64<<<(n * 16 + T - 1) / T, T>>>(x, n);
    k_dis<<<(n + T - 1) / T, T>>>(n);
    k_scanA<<<scanBlocks, SCAN_B>>>(n);
    k_scanB<<<1, SCAN_B>>>(scanBlocks, n);
    k_scanC<<<scanBlocks, SCAN_B>>>(n);
    k_fill<<<(E + T - 1) / T, T>>>(src, dst, E, n);

    const int aggGrid = (n + 7) / 8;      // 8 warps/block
    const int gemmGrid = (n + 127) / 128; // 391

    // Layer 1: (A x)[64] @ W1 -> relu -> fp16 g_f16[128]
    k_agg64_first<<<aggGrid, T>>>(n);                                        // g_f16 -> g_h1
    k_gemm_tc<64, 128, true, true, true><<<gemmGrid, 128>>>(0, 1, b1, 0, n); // g_h1 -> g_f16

    // Layer 2: (A g_f16)[128] @ W2 -> relu -> g_h2[128] fp32
    k_agg128<<<aggGrid, T>>>(n);                                             // g_f16 -> g_h1
    k_gemm_tc<128, 128, true, true, false><<<gemmGrid, 128>>>(0, 1, b2, 16384, n); // g_h1 -> g_h2

    // Layer 3: (g_h2 @ W3)[64] -> fp16 -> aggregate + b3 -> out
    k_gemm_tc<128, 64, false, false, true><<<gemmGrid, 128>>>(1, 0, nullptr, 49152, n); // g_h2 -> g_f16
    k_agg64_last<<<aggGrid, T>>>(out, b3, n);                                // g_f16 -> out
}

// round 10
// speedup vs baseline: 1.1971x; 1.1146x over previous
#include <cuda_runtime.h>
#include <cuda_fp16.h>
#include <cstdint>

#define MAXN 50000
#define MAXE 800000
#define SCAN_B 256
#define MAX_SCAN_BLOCKS ((MAXN + SCAN_B - 1) / SCAN_B)   // 196

// ---------------- scratch (device globals: no allocation allowed) ----------
__device__ __align__(16) int   g_deg[MAXN];
__device__ __align__(16) int   g_cursor[MAXN];
__device__ __align__(16) int   g_rowptr[MAXN + 2];
__device__ __align__(16) float g_dis[MAXN];
__device__ __align__(16) int   g_bsum[MAX_SCAN_BLOCKS + 1];
__device__ __align__(16) int   g_col[MAXE];
__device__ __align__(16) float g_w[MAXE];
__device__ __align__(16) float g_h1[(size_t)MAXN * 128];
__device__ __align__(16) float g_h2[(size_t)MAXN * 128];
__device__ __align__(16) __half g_f16[(size_t)MAXN * 128];  // fp16 agg operand
// tf32 W fragments (single precision, 1xTF32): L1@0 (8192) | L2@8192 (16384) | L3@24576 (8192)
__device__ __align__(16) float g_wfrag[32768];

__device__ __forceinline__ const float* buf_in(int sel)  { return sel == 0 ? g_h1 : g_h2; }
__device__ __forceinline__ float*       buf_out(int sel) { return sel == 0 ? g_h1 : g_h2; }

__device__ __forceinline__ float tf32_rna(float x) {
    unsigned r;
    asm("cvt.rna.tf32.f32 %0, %1;" : "=r"(r) : "f"(x));
    return __uint_as_float(r);
}

__device__ __forceinline__ void mma_tf32(float c[4], float2 A0, float2 A1, float2 B) {
    asm volatile(
        "mma.sync.aligned.m16n8k8.row.col.f32.tf32.tf32.f32 "
        "{%0,%1,%2,%3}, {%4,%5,%6,%7}, {%8,%9}, {%0,%1,%2,%3};"
        : "+f"(c[0]), "+f"(c[1]), "+f"(c[2]), "+f"(c[3])
        : "r"(__float_as_uint(A0.x)), "r"(__float_as_uint(A1.x)),
          "r"(__float_as_uint(A0.y)), "r"(__float_as_uint(A1.y)),
          "r"(__float_as_uint(B.x)),  "r"(__float_as_uint(B.y)));
}

// ---------------- fused init: zero + W-frag prep + x->fp16 ------------------
// One launch, disjoint index ranges (grid = n*16 threads = 800000).
__global__ void k_init(const float* __restrict__ x,
                       const float* __restrict__ W1,
                       const float* __restrict__ W2,
                       const float* __restrict__ W3, int n) {
    int i = blockIdx.x * blockDim.x + threadIdx.x;
    // x conversion: one float4 -> 2x half2
    if (i < n * 16) {
        float4 v = ((const float4*)x)[i];
        __half2* o = (__half2*)g_f16 + i * 2;
        o[0] = __floats2half2_rn(v.x, v.y);
        o[1] = __floats2half2_rn(v.z, v.w);
    }
    // W fragment prep (fragment-order layout, tf32-rounded)
    if (i < 32768) {
        const float* W; int OUT, base, rel;
        if (i < 8192)       { W = W1; OUT = 128; base = 0;     rel = i; }
        else if (i < 24576) { W = W2; OUT = 128; base = 8192;  rel = i - 8192; }
        else                { W = W3; OUT = 64;  base = 24576; rel = i - 24576; }
        int k = rel / OUT, c = rel % OUT;
        int t = k & 3, slot = (k >> 2) & 1;
        int kc = k >> 4, kk = (k >> 3) & 1;
        int off = (((kc * 2 + kk) * OUT + c) << 3) + (t << 1) + slot;
        g_wfrag[base + off] = tf32_rna(W[rel]);
    }
    // zero deg/cursor
    if (i < n) { g_deg[i] = 0; g_cursor[i] = 0; }
}

__global__ void k_count(const int* __restrict__ dst, int E, int n) {
    int i = blockIdx.x * blockDim.x + threadIdx.x;
    if (i < E) {
        unsigned d = (unsigned)dst[i];
        if (d < (unsigned)n) atomicAdd(&g_deg[d], 1);
    }
}

// scanA fused with dis computation
__global__ void k_scanA(int n) {
    __shared__ int sh[SCAN_B];
    int i = blockIdx.x * SCAN_B + threadIdx.x;
    int v = 0;
    if (i < n) {
        v = g_deg[i];
        g_dis[i] = rsqrtf((float)(v + 1));   // +1 self loop
    }
    sh[threadIdx.x] = v;
    __syncthreads();
    for (int off = SCAN_B / 2; off > 0; off >>= 1) {
        if (threadIdx.x < off) sh[threadIdx.x] += sh[threadIdx.x + off];
        __syncthreads();
    }
    if (threadIdx.x == 0) g_bsum[blockIdx.x] = sh[0];
}

__global__ void k_scanB(int nblocks, int n) {
    __shared__ int sh[SCAN_B];
    int t = threadIdx.x;
    int v = (t < nblocks) ? g_bsum[t] : 0;
    sh[t] = v;
    __syncthreads();
    for (int off = 1; off < SCAN_B; off <<= 1) {
        int u = (t >= off) ? sh[t - off] : 0;
        __syncthreads();
        sh[t] += u;
        __syncthreads();
    }
    if (t < nblocks) g_bsum[t] = sh[t] - v;
    if (t == nblocks - 1) g_rowptr[n] = sh[t];
}

__global__ void k_scanC(int n) {
    __shared__ int sh[SCAN_B];
    int i = blockIdx.x * SCAN_B + threadIdx.x;
    int t = threadIdx.x;
    int v = (i < n) ? g_deg[i] : 0;
    sh[t] = v;
    __syncthreads();
    for (int off = 1; off < SCAN_B; off <<= 1) {
        int u = (t >= off) ? sh[t - off] : 0;
        __syncthreads();
        sh[t] += u;
        __syncthreads();
    }
    if (i < n) g_rowptr[i] = sh[t] - v + g_bsum[blockIdx.x];
}

__global__ void k_fill(const int* __restrict__ src,
                       const int* __restrict__ dst, int E, int n) {
    int i = blockIdx.x * blockDim.x + threadIdx.x;
    if (i < E) {
        unsigned s = (unsigned)src[i];
        unsigned d = (unsigned)dst[i];
        if (s < (unsigned)n && d < (unsigned)n) {
            int pos = g_rowptr[d] + atomicAdd(&g_cursor[d], 1);
            g_col[pos] = (int)s;
            g_w[pos] = g_dis[s] * g_dis[d];
        }
    }
}

// ---------------- aggregation (fp16 gathers, fp32 accumulation) -------------
struct __align__(8) h4 { __half2 a, b; };

__global__ void k_agg128(int n) {
    int warp = (blockIdx.x * blockDim.x + threadIdx.x) >> 5;
    int lane = threadIdx.x & 31;
    if (warp >= n) return;
    const __half* in = g_f16;
    float ds = g_dis[warp];
    float self = ds * ds;
    h4 sv = ((const h4*)(in + (size_t)warp * 128))[lane];
    float2 s0 = __half22float2(sv.a), s1 = __half22float2(sv.b);
    float4 acc = make_float4(self * s0.x, self * s0.y, self * s1.x, self * s1.y);
    int beg = g_rowptr[warp], end = g_rowptr[warp + 1];
    for (int base = beg; base < end; base += 32) {
        int idx = base + lane;
        int c = 0; float wv = 0.f;
        if (idx < end) { c = g_col[idx]; wv = g_w[idx]; }
        int m = min(32, end - base);
        for (int t = 0; t < m; t++) {
            int s   = __shfl_sync(0xffffffffu, c, t);
            float w = __shfl_sync(0xffffffffu, wv, t);
            h4 u = ((const h4*)(in + (size_t)s * 128))[lane];
            float2 f0 = __half22float2(u.a), f1 = __half22float2(u.b);
            acc.x += w * f0.x; acc.y += w * f0.y;
            acc.z += w * f1.x; acc.w += w * f1.y;
        }
    }
    ((float4*)(g_h1 + (size_t)warp * 128))[lane] = acc;
}

__global__ void k_agg64_first(int n) {
    int warp = (blockIdx.x * blockDim.x + threadIdx.x) >> 5;
    int lane = threadIdx.x & 31;
    if (warp >= n) return;
    const __half* in = g_f16;
    float ds = g_dis[warp];
    float self = ds * ds;
    float2 v = __half22float2(((const __half2*)(in + (size_t)warp * 64))[lane]);
    float2 acc = make_float2(self * v.x, self * v.y);
    int beg = g_rowptr[warp], end = g_rowptr[warp + 1];
    for (int base = beg; base < end; base += 32) {
        int idx = base + lane;
        int c = 0; float wv = 0.f;
        if (idx < end) { c = g_col[idx]; wv = g_w[idx]; }
        int m = min(32, end - base);
        for (int t = 0; t < m; t++) {
            int s   = __shfl_sync(0xffffffffu, c, t);
            float w = __shfl_sync(0xffffffffu, wv, t);
            float2 u = __half22float2(((const __half2*)(in + (size_t)s * 64))[lane]);
            acc.x += w * u.x; acc.y += w * u.y;
        }
    }
    ((float2*)(g_h1 + (size_t)warp * 64))[lane] = acc;
}

__global__ void k_agg64_last(float* __restrict__ out,
                             const float* __restrict__ bias, int n) {
    int warp = (blockIdx.x * blockDim.x + threadIdx.x) >> 5;
    int lane = threadIdx.x & 31;
    if (warp >= n) return;
    const __half* in = g_f16;
    float ds = g_dis[warp];
    float self = ds * ds;
    float2 v = __half22float2(((const __half2*)(in + (size_t)warp * 64))[lane]);
    float2 acc = make_float2(self * v.x, self * v.y);
    int beg = g_rowptr[warp], end = g_rowptr[warp + 1];
    for (int base = beg; base < end; base += 32) {
        int idx = base + lane;
        int c = 0; float wv = 0.f;
        if (idx < end) { c = g_col[idx]; wv = g_w[idx]; }
        int m = min(32, end - base);
        for (int t = 0; t < m; t++) {
            int s   = __shfl_sync(0xffffffffu, c, t);
            float w = __shfl_sync(0xffffffffu, wv, t);
            float2 u = __half22float2(((const __half2*)(in + (size_t)s * 64))[lane]);
            acc.x += w * u.x; acc.y += w * u.y;
        }
    }
    acc.x += bias[lane * 2];
    acc.y += bias[lane * 2 + 1];
    ((float2*)(out + (size_t)warp * 64))[lane] = acc;
}

// ---------------- tensor-core GEMM (1xTF32) ---------------------------------
// Y[n,OUT] = X[n,IN] @ W[IN,OUT] (+bias)(+relu). rel precision ~tf32 (10-bit
// mantissa, same as the fp16 stages already in the pipeline).
template <int IN, int OUT, bool BIAS, bool RELU, bool HALF_OUT>
__global__ void __launch_bounds__(128) k_gemm_tc(int insel, int outsel,
        const float* __restrict__ bias, int wfb, int n) {
    constexpr int NT = OUT / 8;
    __shared__ float XF[2 * 128 * 8];
    __shared__ float WF[2 * OUT * 8];

    const float* X = buf_in(insel);
    float* Y = buf_out(outsel);
    __half* Y16 = g_f16;
    const float* WG = g_wfrag + wfb;

    int tid = threadIdx.x;
    int w = tid >> 5, lane = tid & 31, g = lane >> 2, t = lane & 3;
    int row0 = blockIdx.x * 128;

    float acc[2][NT][4];
#pragma unroll
    for (int m = 0; m < 2; m++)
#pragma unroll
        for (int nt = 0; nt < NT; nt++)
#pragma unroll
            for (int q = 0; q < 4; q++) acc[m][nt][q] = 0.f;

    for (int kc = 0; kc < IN / 16; kc++) {
        // ---- stage X chunk (tf32-rounded, fragment order) ----
#pragma unroll
        for (int f = 0; f < 4; f++) {
            int fid = tid + f * 128;
            int r = fid >> 2;
            int j = fid & 3;
            float4 v = make_float4(0.f, 0.f, 0.f, 0.f);
            int gr = row0 + r;
            if (gr < n) v = *(const float4*)(X + (size_t)gr * IN + kc * 16 + j * 4);
            int kk = j >> 1, slot = j & 1;
            int b = kk * 1024 + r * 8 + slot;
            XF[b + 0] = tf32_rna(v.x);
            XF[b + 2] = tf32_rna(v.y);
            XF[b + 4] = tf32_rna(v.z);
            XF[b + 6] = tf32_rna(v.w);
        }
        // ---- stage W chunk (contiguous copy) ----
        {
            const float4* s_ = (const float4*)(WG + kc * OUT * 16);
            float4* d_ = (float4*)WF;
            for (int f = tid; f < OUT * 4; f += 128) d_[f] = s_[f];
        }
        __syncthreads();

#pragma unroll
        for (int kk = 0; kk < 2; kk++) {
            float2 a[2][2];
#pragma unroll
            for (int m = 0; m < 2; m++) {
                int r = w * 32 + m * 16 + g;
                a[m][0] = *(const float2*)(XF + kk * 1024 + r * 8 + t * 2);
                a[m][1] = *(const float2*)(XF + kk * 1024 + (r + 8) * 8 + t * 2);
            }
#pragma unroll
            for (int nt = 0; nt < NT; nt++) {
                float2 b = *(const float2*)(WF + kk * OUT * 8 + (nt * 8 + g) * 8 + t * 2);
#pragma unroll
                for (int m = 0; m < 2; m++)
                    mma_tf32(acc[m][nt], a[m][0], a[m][1], b);
            }
        }
        __syncthreads();
    }

    // ---- epilogue ----
#pragma unroll
    for (int m = 0; m < 2; m++) {
        int r = row0 + w * 32 + m * 16 + g;
#pragma unroll
        for (int nt = 0; nt < NT; nt++) {
            int c = nt * 8 + t * 2;
            float2 p0 = make_float2(acc[m][nt][0], acc[m][nt][1]);
            float2 p1 = make_float2(acc[m][nt][2], acc[m][nt][3]);
            if (BIAS) {
                float2 bb = *(const float2*)(bias + c);
                p0.x += bb.x; p0.y += bb.y; p1.x += bb.x; p1.y += bb.y;
            }
            if (RELU) {
                p0.x = fmaxf(p0.x, 0.f); p0.y = fmaxf(p0.y, 0.f);
                p1.x = fmaxf(p1.x, 0.f); p1.y = fmaxf(p1.y, 0.f);
            }
            if (HALF_OUT) {
                if (r < n)
                    *(__half2*)(Y16 + (size_t)r * OUT + c) = __floats2half2_rn(p0.x, p0.y);
                if (r + 8 < n)
                    *(__half2*)(Y16 + (size_t)(r + 8) * OUT + c) = __floats2half2_rn(p1.x, p1.y);
            } else {
                if (r < n)     *(float2*)(Y + (size_t)r * OUT + c) = p0;
                if (r + 8 < n) *(float2*)(Y + (size_t)(r + 8) * OUT + c) = p1;
            }
        }
    }
}

// ---------------- launch ----------------------------------------------------
extern "C" void kernel_launch(void* const* d_in, const int* in_sizes, int n_in,
                              void* d_out, int out_size) {
    const float* x  = (const float*)d_in[0];
    const int*   ei = (const int*)d_in[1];   // int32 (JAX x64 disabled)
    const float* W1 = (const float*)d_in[2];
    const float* b1 = (const float*)d_in[3];
    const float* W2 = (const float*)d_in[4];
    const float* b2 = (const float*)d_in[5];
    const float* W3 = (const float*)d_in[6];
    const float* b3 = (const float*)d_in[7];
    float* out = (float*)d_out;

    const int n = in_sizes[0] / 64;   // 50000
    const int E = in_sizes[1] / 2;    // 800000
    const int* src = ei;
    const int* dst = ei + E;

    const int T = 256;
    const int scanBlocks = (n + SCAN_B - 1) / SCAN_B;   // 196

    // --- preprocessing: 6 launches ---
    k_init<<<(n * 16 + T - 1) / T, T>>>(x, W1, W2, W3, n);
    k_count<<<(E + T - 1) / T, T>>>(dst, E, n);
    k_scanA<<<scanBlocks, SCAN_B>>>(n);
    k_scanB<<<1, SCAN_B>>>(scanBlocks, n);
    k_scanC<<<scanBlocks, SCAN_B>>>(n);
    k_fill<<<(E + T - 1) / T, T>>>(src, dst, E, n);

    const int aggGrid = (n + 7) / 8;      // 8 warps/block
    const int gemmGrid = (n + 127) / 128; // 391

    // Layer 1: (A x)[64] @ W1 -> relu -> fp16 g_f16[128]
    k_agg64_first<<<aggGrid, T>>>(n);                                        // g_f16 -> g_h1
    k_gemm_tc<64, 128, true, true, true><<<gemmGrid, 128>>>(0, 1, b1, 0, n); // g_h1 -> g_f16

    // Layer 2: (A g_f16)[128] @ W2 -> relu -> g_h2[128] fp32
    k_agg128<<<aggGrid, T>>>(n);                                             // g_f16 -> g_h1
    k_gemm_tc<128, 128, true, true, false><<<gemmGrid, 128>>>(0, 1, b2, 8192, n); // g_h1 -> g_h2

    // Layer 3: (g_h2 @ W3)[64] -> fp16 -> aggregate + b3 -> out
    k_gemm_tc<128, 64, false, false, true><<<gemmGrid, 128>>>(1, 0, nullptr, 24576, n); // g_h2 -> g_f16
    k_agg64_last<<<aggGrid, T>>>(out, b3, n);                                // g_f16 -> out
}

// round 11
// speedup vs baseline: 1.6652x; 1.3910x over previous
#include <cuda_runtime.h>
#include <cuda_fp16.h>
#include <cstdint>

#define MAXN 50000
#define MAXE 800000

// ---------------- scratch (device globals: no allocation allowed) ----------
__device__ __align__(16) int    g_deg[MAXN];
__device__ __align__(16) int    g_cursor[MAXN];
__device__ __align__(16) int    g_rowbeg[MAXN];
__device__ __align__(16) float  g_dis[MAXN];
__device__ __align__(16) int    g_col[MAXE];
__device__ __align__(16) float  g_w[MAXE];
__device__ int g_etot;
// ping-pong fp16 feature buffers (padded 128 rows: GEMM reads whole 128-row
// tiles unguarded; stores are guarded)
__device__ __align__(16) __half g_fa[(size_t)(MAXN + 128) * 128];
__device__ __align__(16) __half g_fb[(size_t)(MAXN + 128) * 128];
// fp16 W fragments (m16n8k16 B-fragment order):
// L1@0 (8192 halfs) | L2@8192 (16384) | L3@24576 (8192)
__device__ __align__(16) __half g_wf16[32768];

// fp16 MMA: D(16x8,f32) += A(16x16,f16) * B(16x8,f16)
__device__ __forceinline__ void mma_f16(float c[4], const unsigned a[4], uint2 b) {
    asm volatile(
        "mma.sync.aligned.m16n8k16.row.col.f32.f16.f16.f32 "
        "{%0,%1,%2,%3}, {%4,%5,%6,%7}, {%8,%9}, {%0,%1,%2,%3};"
        : "+f"(c[0]), "+f"(c[1]), "+f"(c[2]), "+f"(c[3])
        : "r"(a[0]), "r"(a[1]), "r"(a[2]), "r"(a[3]), "r"(b.x), "r"(b.y));
}

// ---------------- k_init: zero + W fp16 frags + x->fp16 ---------------------
__global__ void k_init(const float* __restrict__ x,
                       const float* __restrict__ W1,
                       const float* __restrict__ W2,
                       const float* __restrict__ W3, int n) {
    int i = blockIdx.x * blockDim.x + threadIdx.x;
    if (i == 0) g_etot = 0;
    // x [n,64] fp32 -> g_fb fp16 (one float4 -> 2 half2)
    if (i < n * 16) {
        float4 v = ((const float4*)x)[i];
        __half2* o = (__half2*)g_fb + i * 2;
        o[0] = __floats2half2_rn(v.x, v.y);
        o[1] = __floats2half2_rn(v.z, v.w);
    }
    // W -> fp16 fragment order. Thread t of a quad owns k = {2t,2t+1,2t+8,2t+9}
    // within each 16-chunk; store those 4 halfs contiguously per (kc, n).
    if (i < 32768) {
        const float* W; int OUT, base, rel;
        if (i < 8192)       { W = W1; OUT = 128; base = 0;     rel = i; }
        else if (i < 24576) { W = W2; OUT = 128; base = 8192;  rel = i - 8192; }
        else                { W = W3; OUT = 64;  base = 24576; rel = i - 24576; }
        int k = rel / OUT, c = rel % OUT;
        int kc = k >> 4, kr = k & 15;
        int t   = (kr < 8) ? (kr >> 1) : ((kr - 8) >> 1);
        int pos = (kr < 8) ? (kr & 1) : (2 + (kr & 1));
        g_wf16[base + ((kc * OUT + c) << 4) + (t << 2) + pos] = __float2half(W[rel]);
    }
    if (i < n) { g_deg[i] = 0; g_cursor[i] = 0; }
}

__global__ void k_count(const int* __restrict__ dst, int E, int n) {
    int i = blockIdx.x * blockDim.x + threadIdx.x;
    if (i < E) {
        unsigned d = (unsigned)dst[i];
        if (d < (unsigned)n) atomicAdd(&g_deg[d], 1);
    }
}

// rows get disjoint contiguous ranges via warp-aggregated atomic allocation;
// ordering is irrelevant for gather. Also computes dis.
__global__ void k_alloc(int n) {
    int i = blockIdx.x * blockDim.x + threadIdx.x;
    int lane = threadIdx.x & 31;
    int d = 0;
    if (i < n) {
        d = g_deg[i];
        g_dis[i] = rsqrtf((float)(d + 1));   // +1 self loop
    }
    int scan = d;
#pragma unroll
    for (int off = 1; off < 32; off <<= 1) {
        int v = __shfl_up_sync(0xffffffffu, scan, off);
        if (lane >= off) scan += v;
    }
    int tot = __shfl_sync(0xffffffffu, scan, 31);
    int base = 0;
    if (lane == 0) base = atomicAdd(&g_etot, tot);
    base = __shfl_sync(0xffffffffu, base, 0);
    if (i < n) g_rowbeg[i] = base + scan - d;
}

__global__ void k_fill(const int* __restrict__ src,
                       const int* __restrict__ dst, int E, int n) {
    int i = blockIdx.x * blockDim.x + threadIdx.x;
    if (i < E) {
        unsigned s = (unsigned)src[i];
        unsigned d = (unsigned)dst[i];
        if (s < (unsigned)n && d < (unsigned)n) {
            int pos = g_rowbeg[d] + atomicAdd(&g_cursor[d], 1);
            g_col[pos] = (int)s;
            g_w[pos] = g_dis[s] * g_dis[d];
        }
    }
}

// ---------------- aggregation (fp16 in fb -> fp16 out fa, fp32 accum) -------
struct __align__(8) h4 { __half2 a, b; };

__global__ void k_agg128(int n) {
    int warp = (blockIdx.x * blockDim.x + threadIdx.x) >> 5;
    int lane = threadIdx.x & 31;
    if (warp >= n) return;
    const __half* in = g_fb;
    float ds = g_dis[warp];
    float self = ds * ds;
    h4 sv = ((const h4*)(in + (size_t)warp * 128))[lane];
    float2 s0 = __half22float2(sv.a), s1 = __half22float2(sv.b);
    float4 acc = make_float4(self * s0.x, self * s0.y, self * s1.x, self * s1.y);
    int beg = g_rowbeg[warp], end = beg + g_deg[warp];
    for (int base = beg; base < end; base += 32) {
        int idx = base + lane;
        int c = 0; float wv = 0.f;
        if (idx < end) { c = g_col[idx]; wv = g_w[idx]; }
        int m = min(32, end - base);
        for (int t = 0; t < m; t++) {
            int s   = __shfl_sync(0xffffffffu, c, t);
            float w = __shfl_sync(0xffffffffu, wv, t);
            h4 u = ((const h4*)(in + (size_t)s * 128))[lane];
            float2 f0 = __half22float2(u.a), f1 = __half22float2(u.b);
            acc.x += w * f0.x; acc.y += w * f0.y;
            acc.z += w * f1.x; acc.w += w * f1.y;
        }
    }
    h4 o;
    o.a = __floats2half2_rn(acc.x, acc.y);
    o.b = __floats2half2_rn(acc.z, acc.w);
    ((h4*)(g_fa + (size_t)warp * 128))[lane] = o;
}

__global__ void k_agg64_first(int n) {
    int warp = (blockIdx.x * blockDim.x + threadIdx.x) >> 5;
    int lane = threadIdx.x & 31;
    if (warp >= n) return;
    const __half* in = g_fb;
    float ds = g_dis[warp];
    float self = ds * ds;
    float2 v = __half22float2(((const __half2*)(in + (size_t)warp * 64))[lane]);
    float2 acc = make_float2(self * v.x, self * v.y);
    int beg = g_rowbeg[warp], end = beg + g_deg[warp];
    for (int base = beg; base < end; base += 32) {
        int idx = base + lane;
        int c = 0; float wv = 0.f;
        if (idx < end) { c = g_col[idx]; wv = g_w[idx]; }
        int m = min(32, end - base);
        for (int t = 0; t < m; t++) {
            int s   = __shfl_sync(0xffffffffu, c, t);
            float w = __shfl_sync(0xffffffffu, wv, t);
            float2 u = __half22float2(((const __half2*)(in + (size_t)s * 64))[lane]);
            acc.x += w * u.x; acc.y += w * u.y;
        }
    }
    ((__half2*)(g_fa + (size_t)warp * 64))[lane] = __floats2half2_rn(acc.x, acc.y);
}

// last agg reads g_fa (GEMM3 output), writes fp32 out + bias
__global__ void k_agg64_last(float* __restrict__ out,
                             const float* __restrict__ bias, int n) {
    int warp = (blockIdx.x * blockDim.x + threadIdx.x) >> 5;
    int lane = threadIdx.x & 31;
    if (warp >= n) return;
    const __half* in = g_fa;
    float ds = g_dis[warp];
    float self = ds * ds;
    float2 v = __half22float2(((const __half2*)(in + (size_t)warp * 64))[lane]);
    float2 acc = make_float2(self * v.x, self * v.y);
    int beg = g_rowbeg[warp], end = beg + g_deg[warp];
    for (int base = beg; base < end; base += 32) {
        int idx = base + lane;
        int c = 0; float wv = 0.f;
        if (idx < end) { c = g_col[idx]; wv = g_w[idx]; }
        int m = min(32, end - base);
        for (int t = 0; t < m; t++) {
            int s   = __shfl_sync(0xffffffffu, c, t);
            float w = __shfl_sync(0xffffffffu, wv, t);
            float2 u = __half22float2(((const __half2*)(in + (size_t)s * 64))[lane]);
            acc.x += w * u.x; acc.y += w * u.y;
        }
    }
    acc.x += bias[lane * 2];
    acc.y += bias[lane * 2 + 1];
    ((float2*)(out + (size_t)warp * 64))[lane] = acc;
}

// ---------------- smem-free fp16 tensor GEMM --------------------------------
// Y(g_fb or g_fa) = X @ W (+bias)(+relu), all fp16 with fp32 accum.
// Warp-private A rows loaded directly from gmem; W fragments from the
// L1-resident precomputed table. No shared memory, no barriers.
// DIR: 0 = read g_fa / write g_fb;  1 = read g_fb / write g_fa
template <int IN, int OUT, bool BIAS, bool RELU, int DIR>
__global__ void __launch_bounds__(128) k_gemm16(const float* __restrict__ bias,
                                                int wbase, int n) {
    constexpr int NT = OUT / 8;
    const __half* X = DIR == 0 ? g_fa : g_fb;
    __half* Y = DIR == 0 ? g_fb : g_fa;
    const __half* WF = g_wf16 + wbase;

    int tid = threadIdx.x;
    int w = tid >> 5, lane = tid & 31, g = lane >> 2, t = lane & 3;
    int row0 = blockIdx.x * 128 + w * 32 + g;

    float acc[2][NT][4];
#pragma unroll
    for (int m = 0; m < 2; m++)
#pragma unroll
        for (int nt = 0; nt < NT; nt++)
#pragma unroll
            for (int q = 0; q < 4; q++) acc[m][nt][q] = 0.f;

#pragma unroll
    for (int kc = 0; kc < IN / 16; kc++) {
        unsigned a[2][4];
#pragma unroll
        for (int m = 0; m < 2; m++) {
            size_t r = (size_t)(row0 + m * 16);
            const __half* xp = X + r * IN + kc * 16 + 2 * t;
            a[m][0] = *(const unsigned*)(xp);                // (r,   2t..2t+1)
            a[m][1] = *(const unsigned*)(xp + 8 * IN);       // (r+8, 2t..2t+1)
            a[m][2] = *(const unsigned*)(xp + 8);            // (r,   2t+8..+9)
            a[m][3] = *(const unsigned*)(xp + 8 * IN + 8);   // (r+8, 2t+8..+9)
        }
#pragma unroll
        for (int nt = 0; nt < NT; nt++) {
            uint2 b = *(const uint2*)(WF + ((kc * OUT + nt * 8 + g) << 4) + (t << 2));
            mma_f16(acc[0][nt], a[0], b);
            mma_f16(acc[1][nt], a[1], b);
        }
    }

#pragma unroll
    for (int m = 0; m < 2; m++) {
        int r = row0 + m * 16;
#pragma unroll
        for (int nt = 0; nt < NT; nt++) {
            int c = nt * 8 + t * 2;
            float2 p0 = make_float2(acc[m][nt][0], acc[m][nt][1]);
            float2 p1 = make_float2(acc[m][nt][2], acc[m][nt][3]);
            if (BIAS) {
                float2 bb = *(const float2*)(bias + c);
                p0.x += bb.x; p0.y += bb.y; p1.x += bb.x; p1.y += bb.y;
            }
            if (RELU) {
                p0.x = fmaxf(p0.x, 0.f); p0.y = fmaxf(p0.y, 0.f);
                p1.x = fmaxf(p1.x, 0.f); p1.y = fmaxf(p1.y, 0.f);
            }
            if (r < n)
                *(__half2*)(Y + (size_t)r * OUT + c) = __floats2half2_rn(p0.x, p0.y);
            if (r + 8 < n)
                *(__half2*)(Y + (size_t)(r + 8) * OUT + c) = __floats2half2_rn(p1.x, p1.y);
        }
    }
}

// ---------------- launch ----------------------------------------------------
extern "C" void kernel_launch(void* const* d_in, const int* in_sizes, int n_in,
                              void* d_out, int out_size) {
    const float* x  = (const float*)d_in[0];
    const int*   ei = (const int*)d_in[1];   // int32 (JAX x64 disabled)
    const float* W1 = (const float*)d_in[2];
    const float* b1 = (const float*)d_in[3];
    const float* W2 = (const float*)d_in[4];
    const float* b2 = (const float*)d_in[5];
    const float* W3 = (const float*)d_in[6];
    const float* b3 = (const float*)d_in[7];
    float* out = (float*)d_out;

    const int n = in_sizes[0] / 64;   // 50000
    const int E = in_sizes[1] / 2;    // 800000
    const int* src = ei;
    const int* dst = ei + E;

    const int T = 256;

    // --- preprocessing: 4 launches ---
    k_init<<<(n * 16 + T - 1) / T, T>>>(x, W1, W2, W3, n);  // x -> g_fb
    k_count<<<(E + T - 1) / T, T>>>(dst, E, n);
    k_alloc<<<(n + T - 1) / T, T>>>(n);
    k_fill<<<(E + T - 1) / T, T>>>(src, dst, E, n);

    const int aggGrid = (n + 7) / 8;      // 8 warps/block
    const int gemmGrid = (n + 127) / 128; // 391

    // L1: agg(x) -> fa ; fa @ W1 +b1 relu -> fb
    k_agg64_first<<<aggGrid, T>>>(n);
    k_gemm16<64, 128, true, true, 0><<<gemmGrid, 128>>>(b1, 0, n);

    // L2: agg(fb) -> fa ; fa @ W2 +b2 relu -> fb
    k_agg128<<<aggGrid, T>>>(n);
    k_gemm16<128, 128, true, true, 0><<<gemmGrid, 128>>>(b2, 8192, n);

    // L3: fb @ W3 -> fa ; agg(fa) + b3 -> out
    k_gemm16<128, 64, false, false, 1><<<gemmGrid, 128>>>(nullptr, 24576, n);
    k_agg64_last<<<aggGrid, T>>>(out, b3, n);
}